// round 1
// baseline (speedup 1.0000x reference)
#include <cuda_runtime.h>

#define BB 4
#define LL 5
#define CC 256
#define HW 25200
#define KSEL 1024
#define NSLICE (BB*LL)
#define HW4 (HW/4)

// scratch (no allocations allowed)
__device__ unsigned g_keys[NSLICE * HW];      // order-preserving uint keys of fmap
__device__ unsigned g_fmask[NSLICE * HW4];    // 4 bytes per uint, 1 byte per hw

__device__ __forceinline__ unsigned f2ord(float f) {
    unsigned u = __float_as_uint(f);
    // monotone float -> uint map (works for +/-/0)
    return u ^ ((unsigned)((int)u >> 31) | 0x80000000u);
}

// Kernel 1: keys[slice*HW + hw] = ord(max_c(psm[b,l,c,hw] - psm[b,0,c,hw]))
__global__ void compute_keys_kernel(const float* __restrict__ psm) {
    int i = blockIdx.x * blockDim.x + threadIdx.x;
    if (i >= NSLICE * HW) return;
    int slice = i / HW;
    int hw    = i - slice * HW;
    int b     = slice / LL;
    const float* pl = psm + (size_t)slice * 2 * HW + hw;          // (b,l,0,hw)
    const float* p0 = psm + (size_t)(b * LL) * 2 * HW + hw;       // (b,0,0,hw)
    float d0 = pl[0]  - p0[0];
    float d1 = pl[HW] - p0[HW];
    g_keys[i] = f2ord(fmaxf(d0, d1));
}

// Kernel 2: per-slice radix select of K-th largest key, then write byte mask.
__global__ void select_and_mask_kernel() {
    __shared__ unsigned hist[2048];
    __shared__ unsigned s_prefix;
    __shared__ int s_k;

    const int slice = blockIdx.x;
    const unsigned* keys = g_keys + slice * HW;
    const int tid = threadIdx.x;

    if (tid == 0) { s_prefix = 0u; s_k = KSEL; }
    unsigned decided = 0u;

    const int shifts[3] = {21, 10, 0};
    const int nbitsA[3] = {11, 11, 10};

    #pragma unroll
    for (int p = 0; p < 3; ++p) {
        const int shift = shifts[p];
        const unsigned bm = (1u << nbitsA[p]) - 1u;
        const int nb = 1 << nbitsA[p];

        for (int j = tid; j < 2048; j += blockDim.x) hist[j] = 0u;
        __syncthreads();

        const unsigned prefix = s_prefix;
        for (int j = tid; j < HW; j += blockDim.x) {
            unsigned u = keys[j];
            if ((u & decided) == prefix)
                atomicAdd(&hist[(u >> shift) & bm], 1u);
        }
        __syncthreads();

        if (tid == 0) {
            int k = s_k;
            int acc = 0, sel = 0;
            for (int bb = nb - 1; bb >= 0; --bb) {
                int h = (int)hist[bb];
                if (acc + h >= k) { sel = bb; s_k = k - acc; break; }
                acc += h;
            }
            s_prefix = prefix | ((unsigned)sel << shift);
        }
        decided |= bm << shift;
        __syncthreads();
    }

    const unsigned thresh = s_prefix;   // exact K-th largest key value
    unsigned* fm = g_fmask + slice * HW4;
    for (int j4 = tid; j4 < HW4; j4 += blockDim.x) {
        const unsigned* kk = keys + j4 * 4;
        unsigned b0 = (kk[0] >= thresh) ? 1u : 0u;
        unsigned b1 = (kk[1] >= thresh) ? 1u : 0u;
        unsigned b2 = (kk[2] >= thresh) ? 1u : 0u;
        unsigned b3 = (kk[3] >= thresh) ? 1u : 0u;
        fm[j4] = b0 | (b1 << 8) | (b2 << 16) | (b3 << 24);
    }
}

// Kernel 3: streaming apply.
// grid: (ceil(HW4/256), C, NSLICE), block 256. One float4 per thread.
__global__ void apply_kernel(const float* __restrict__ x,
                             const int* __restrict__ mask,
                             float* __restrict__ out) {
    int hw4 = blockIdx.x * blockDim.x + threadIdx.x;
    if (hw4 >= HW4) return;
    const int c = blockIdx.y;
    const int slice = blockIdx.z;
    const int l = slice % LL;

    size_t idx = ((size_t)slice * CC + c) * HW + (size_t)hw4 * 4;
    const float4* xv = (const float4*)(x + idx);
    float4* ov = (float4*)(out + idx);

    if (l == 0) { *ov = *xv; return; }
    if (mask[slice] == 0) { *ov = make_float4(0.f, 0.f, 0.f, 0.f); return; }

    float4 v = *xv;
    unsigned m4 = g_fmask[slice * HW4 + hw4];
    v.x = (m4 & 0x000000FFu) ? v.x : 0.0f;
    v.y = (m4 & 0x0000FF00u) ? v.y : 0.0f;
    v.z = (m4 & 0x00FF0000u) ? v.z : 0.0f;
    v.w = (m4 & 0xFF000000u) ? v.w : 0.0f;
    *ov = v;
}

extern "C" void kernel_launch(void* const* d_in, const int* in_sizes, int n_in,
                              void* d_out, int out_size) {
    // Identify inputs by element count (robust to ordering):
    //   x: 129024000, psm: 1008000, mask: 20
    const float* x = nullptr;
    const float* psm = nullptr;
    const int* mask = nullptr;
    for (int i = 0; i < n_in; ++i) {
        if (in_sizes[i] == BB * LL * CC * HW)      x    = (const float*)d_in[i];
        else if (in_sizes[i] == BB * LL * 2 * HW)  psm  = (const float*)d_in[i];
        else if (in_sizes[i] == BB * LL)           mask = (const int*)d_in[i];
    }
    float* out = (float*)d_out;

    compute_keys_kernel<<<(NSLICE * HW + 255) / 256, 256>>>(psm);
    select_and_mask_kernel<<<NSLICE, 256>>>();
    apply_kernel<<<dim3((HW4 + 255) / 256, CC, NSLICE), 256>>>(x, mask, out);
}

// round 2
// speedup vs baseline: 2.2744x; 2.2744x over previous
#include <cuda_runtime.h>

#define BB 4
#define LL 5
#define CC 256
#define HW 25200
#define KSEL 1024
#define NSLICE (BB*LL)
#define HW4 (HW/4)
#define UN 4          // float4s per thread in apply
#define APPLY_T 256

// scratch (no allocations allowed)
__device__ unsigned g_fmask[NSLICE * HW4];    // 4 bytes per uint, 1 byte per hw

__device__ __forceinline__ unsigned f2ord(float f) {
    unsigned u = __float_as_uint(f);
    return u ^ ((unsigned)((int)u >> 31) | 0x80000000u);  // monotone float->uint
}

// Fused: compute keys (smem-resident), 3-pass radix select of K-th largest,
// write byte mask. One block per (b,l) slice.
__global__ void select_kernel(const float* __restrict__ psm) {
    extern __shared__ unsigned sm[];
    unsigned* keys = sm;              // HW
    unsigned* hist = sm + HW;         // 2048
    unsigned* aux  = hist + 2048;     // 2048
    __shared__ unsigned s_prefix;
    __shared__ int s_k, s_sel;

    const int slice = blockIdx.x;
    const int b = slice / LL;
    const int tid = threadIdx.x;
    const int nt = blockDim.x;

    const float* __restrict__ pl = psm + (size_t)slice * 2 * HW;     // (b,l,0,:)
    const float* __restrict__ p0 = psm + (size_t)(b * LL) * 2 * HW;  // (b,0,0,:)
    for (int j = tid; j < HW; j += nt) {
        float d0 = pl[j]      - p0[j];
        float d1 = pl[j + HW] - p0[j + HW];
        keys[j] = f2ord(fmaxf(d0, d1));
    }
    if (tid == 0) { s_prefix = 0u; s_k = KSEL; }
    unsigned decided = 0u;
    __syncthreads();

    const int shifts[3] = {21, 10, 0};
    const int nbitsA[3] = {11, 11, 10};

    #pragma unroll
    for (int p = 0; p < 3; ++p) {
        const int shift = shifts[p];
        const int nb = 1 << nbitsA[p];
        const unsigned bm = (unsigned)nb - 1u;

        for (int j = tid; j < nb; j += nt) hist[j] = 0u;
        __syncthreads();

        const unsigned prefix = s_prefix;
        const int k = s_k;   // stable since previous pass's final barrier
        for (int j = tid; j < HW; j += nt) {
            unsigned u = keys[j];
            if ((u & decided) == prefix)
                atomicAdd(&hist[(u >> shift) & bm], 1u);
        }
        __syncthreads();

        // parallel suffix-sum over nb bins (ping-pong hist<->aux)
        unsigned* src = hist;
        unsigned* dst = aux;
        for (int d = 1; d < nb; d <<= 1) {
            for (int j = tid; j < nb; j += nt)
                dst[j] = src[j] + ((j + d < nb) ? src[j + d] : 0u);
            __syncthreads();
            unsigned* t = src; src = dst; dst = t;
        }
        // src[j] = count of keys with digit >= j (within prefix class)
        for (int j = tid; j < nb; j += nt) {
            int sj  = (int)src[j];
            int sj1 = (j + 1 < nb) ? (int)src[j + 1] : 0;
            if (sj >= k && sj1 < k) {       // unique j
                s_sel = j;
                s_k   = k - sj1;
            }
        }
        __syncthreads();
        if (tid == 0) s_prefix = prefix | ((unsigned)s_sel << shift);
        decided |= bm << shift;
        __syncthreads();
    }

    const unsigned thresh = s_prefix;   // exact K-th largest key
    unsigned* fm = g_fmask + slice * HW4;
    const uint4* k4 = (const uint4*)keys;
    for (int j4 = tid; j4 < HW4; j4 += nt) {
        uint4 kk = k4[j4];
        unsigned b0 = (kk.x >= thresh) ? 1u : 0u;
        unsigned b1 = (kk.y >= thresh) ? 1u : 0u;
        unsigned b2 = (kk.z >= thresh) ? 1u : 0u;
        unsigned b3 = (kk.w >= thresh) ? 1u : 0u;
        fm[j4] = b0 | (b1 << 8) | (b2 << 16) | (b3 << 24);
    }
}

// Streaming apply: grid (ceil(HW4/(T*UN)), C, NSLICE), UN independent float4
// per thread for MLP; streaming cache hints on the 619MB x/out stream.
__global__ void apply_kernel(const float* __restrict__ x,
                             const int* __restrict__ mask,
                             float* __restrict__ out) {
    const int slice = blockIdx.z;
    const int c = blockIdx.y;
    const int l = slice % LL;
    const size_t base = ((size_t)slice * CC + c) * (size_t)HW4;
    const float4* __restrict__ xv = (const float4*)x + base;
    float4* __restrict__ ov = (float4*)out + base;
    const int j0 = blockIdx.x * (APPLY_T * UN) + threadIdx.x;

    if (l == 0) {
        #pragma unroll
        for (int u = 0; u < UN; ++u) {
            int j = j0 + u * APPLY_T;
            if (j < HW4) __stcs(ov + j, __ldcs(xv + j));
        }
        return;
    }
    if (mask[slice] == 0) {
        const float4 z = make_float4(0.f, 0.f, 0.f, 0.f);
        #pragma unroll
        for (int u = 0; u < UN; ++u) {
            int j = j0 + u * APPLY_T;
            if (j < HW4) __stcs(ov + j, z);
        }
        return;
    }
    const unsigned* __restrict__ fm = g_fmask + slice * HW4;
    float4 v[UN];
    unsigned m4[UN];
    #pragma unroll
    for (int u = 0; u < UN; ++u) {
        int j = j0 + u * APPLY_T;
        if (j < HW4) { v[u] = __ldcs(xv + j); m4[u] = fm[j]; }
    }
    #pragma unroll
    for (int u = 0; u < UN; ++u) {
        int j = j0 + u * APPLY_T;
        if (j < HW4) {
            float4 w = v[u];
            unsigned m = m4[u];
            w.x = (m & 0x000000FFu) ? w.x : 0.0f;
            w.y = (m & 0x0000FF00u) ? w.y : 0.0f;
            w.z = (m & 0x00FF0000u) ? w.z : 0.0f;
            w.w = (m & 0xFF000000u) ? w.w : 0.0f;
            __stcs(ov + j, w);
        }
    }
}

extern "C" void kernel_launch(void* const* d_in, const int* in_sizes, int n_in,
                              void* d_out, int out_size) {
    const float* x = nullptr;
    const float* psm = nullptr;
    const int* mask = nullptr;
    for (int i = 0; i < n_in; ++i) {
        if (in_sizes[i] == BB * LL * CC * HW)      x    = (const float*)d_in[i];
        else if (in_sizes[i] == BB * LL * 2 * HW)  psm  = (const float*)d_in[i];
        else if (in_sizes[i] == BB * LL)           mask = (const int*)d_in[i];
    }
    float* out = (float*)d_out;

    const int sel_smem = (HW + 2048 + 2048) * (int)sizeof(unsigned);  // ~117KB
    cudaFuncSetAttribute(select_kernel,
                         cudaFuncAttributeMaxDynamicSharedMemorySize, sel_smem);

    select_kernel<<<NSLICE, 1024, sel_smem>>>(psm);

    const int gx = (HW4 + APPLY_T * UN - 1) / (APPLY_T * UN);  // 7
    apply_kernel<<<dim3(gx, CC, NSLICE), APPLY_T>>>(x, mask, out);
}

// round 3
// speedup vs baseline: 2.4412x; 1.0733x over previous
#include <cuda_runtime.h>

#define BB 4
#define LL 5
#define CC 256
#define HW 25200
#define KSEL 1024
#define NSLICE (BB*LL)
#define HW4 (HW/4)
#define UN 4          // float4s per thread in apply
#define APPLY_T 256

// scratch (no allocations allowed)
__device__ unsigned g_fmask[NSLICE * HW4];    // 4 bytes per uint, 1 byte per hw

__device__ __forceinline__ unsigned f2ord(float f) {
    unsigned u = __float_as_uint(f);
    return u ^ ((unsigned)((int)u >> 31) | 0x80000000u);  // monotone float->uint
}

// Fused: compute keys (smem-resident), 3-pass radix select of K-th largest,
// write byte mask. One block per (b,l) slice.
__global__ void select_kernel(const float* __restrict__ psm) {
    extern __shared__ unsigned sm[];
    unsigned* keys = sm;              // HW
    unsigned* hist = sm + HW;         // 2048
    unsigned* aux  = hist + 2048;     // 2048
    __shared__ unsigned s_prefix;
    __shared__ int s_k, s_sel;

    const int slice = blockIdx.x;
    const int b = slice / LL;
    const int tid = threadIdx.x;
    const int nt = blockDim.x;

    const float* __restrict__ pl = psm + (size_t)slice * 2 * HW;     // (b,l,0,:)
    const float* __restrict__ p0 = psm + (size_t)(b * LL) * 2 * HW;  // (b,0,0,:)
    for (int j = tid; j < HW; j += nt) {
        float d0 = pl[j]      - p0[j];
        float d1 = pl[j + HW] - p0[j + HW];
        keys[j] = f2ord(fmaxf(d0, d1));
    }
    if (tid == 0) { s_prefix = 0u; s_k = KSEL; }
    unsigned decided = 0u;
    __syncthreads();

    const int shifts[3] = {21, 10, 0};
    const int nbitsA[3] = {11, 11, 10};

    #pragma unroll
    for (int p = 0; p < 3; ++p) {
        const int shift = shifts[p];
        const int nb = 1 << nbitsA[p];
        const unsigned bm = (unsigned)nb - 1u;

        for (int j = tid; j < nb; j += nt) hist[j] = 0u;
        __syncthreads();

        const unsigned prefix = s_prefix;
        const int k = s_k;   // stable since previous pass's final barrier
        for (int j = tid; j < HW; j += nt) {
            unsigned u = keys[j];
            if ((u & decided) == prefix)
                atomicAdd(&hist[(u >> shift) & bm], 1u);
        }
        __syncthreads();

        // parallel suffix-sum over nb bins (ping-pong hist<->aux)
        unsigned* src = hist;
        unsigned* dst = aux;
        for (int d = 1; d < nb; d <<= 1) {
            for (int j = tid; j < nb; j += nt)
                dst[j] = src[j] + ((j + d < nb) ? src[j + d] : 0u);
            __syncthreads();
            unsigned* t = src; src = dst; dst = t;
        }
        // src[j] = count of keys with digit >= j (within prefix class)
        for (int j = tid; j < nb; j += nt) {
            int sj  = (int)src[j];
            int sj1 = (j + 1 < nb) ? (int)src[j + 1] : 0;
            if (sj >= k && sj1 < k) {       // unique j
                s_sel = j;
                s_k   = k - sj1;
            }
        }
        __syncthreads();
        if (tid == 0) s_prefix = prefix | ((unsigned)s_sel << shift);
        decided |= bm << shift;
        __syncthreads();
    }

    const unsigned thresh = s_prefix;   // exact K-th largest key
    unsigned* fm = g_fmask + slice * HW4;
    const uint4* k4 = (const uint4*)keys;
    for (int j4 = tid; j4 < HW4; j4 += nt) {
        uint4 kk = k4[j4];
        unsigned b0 = (kk.x >= thresh) ? 1u : 0u;
        unsigned b1 = (kk.y >= thresh) ? 1u : 0u;
        unsigned b2 = (kk.z >= thresh) ? 1u : 0u;
        unsigned b3 = (kk.w >= thresh) ? 1u : 0u;
        fm[j4] = b0 | (b1 << 8) | (b2 << 16) | (b3 << 24);
    }
}

// Easy slices: l==0 -> copy x, (l>0 && mask==0) -> zeros. No fmask dependency.
// grid (ceil(HW4/(T*UN)), C, NSLICE)
__global__ void apply_easy_kernel(const float* __restrict__ x,
                                  const int* __restrict__ mask,
                                  float* __restrict__ out) {
    const int slice = blockIdx.z;
    const int l = slice % LL;
    const bool is_ego = (l == 0);
    if (!is_ego && mask[slice] != 0) return;   // masked path handled later

    const int c = blockIdx.y;
    const size_t base = ((size_t)slice * CC + c) * (size_t)HW4;
    const float4* __restrict__ xv = (const float4*)x + base;
    float4* __restrict__ ov = (float4*)out + base;
    const int j0 = blockIdx.x * (APPLY_T * UN) + threadIdx.x;

    if (is_ego) {
        #pragma unroll
        for (int u = 0; u < UN; ++u) {
            int j = j0 + u * APPLY_T;
            if (j < HW4) __stcs(ov + j, __ldcs(xv + j));
        }
    } else {
        const float4 z = make_float4(0.f, 0.f, 0.f, 0.f);
        #pragma unroll
        for (int u = 0; u < UN; ++u) {
            int j = j0 + u * APPLY_T;
            if (j < HW4) __stcs(ov + j, z);
        }
    }
}

// Masked slices: l>0 && mask!=0 -> x * fmask.
__global__ void apply_masked_kernel(const float* __restrict__ x,
                                    const int* __restrict__ mask,
                                    float* __restrict__ out) {
    const int slice = blockIdx.z;
    const int l = slice % LL;
    if (l == 0 || mask[slice] == 0) return;    // handled by easy kernel

    const int c = blockIdx.y;
    const size_t base = ((size_t)slice * CC + c) * (size_t)HW4;
    const float4* __restrict__ xv = (const float4*)x + base;
    float4* __restrict__ ov = (float4*)out + base;
    const int j0 = blockIdx.x * (APPLY_T * UN) + threadIdx.x;

    const unsigned* __restrict__ fm = g_fmask + slice * HW4;
    float4 v[UN];
    unsigned m4[UN];
    #pragma unroll
    for (int u = 0; u < UN; ++u) {
        int j = j0 + u * APPLY_T;
        if (j < HW4) { v[u] = __ldcs(xv + j); m4[u] = fm[j]; }
    }
    #pragma unroll
    for (int u = 0; u < UN; ++u) {
        int j = j0 + u * APPLY_T;
        if (j < HW4) {
            float4 w = v[u];
            unsigned m = m4[u];
            w.x = (m & 0x000000FFu) ? w.x : 0.0f;
            w.y = (m & 0x0000FF00u) ? w.y : 0.0f;
            w.z = (m & 0x00FF0000u) ? w.z : 0.0f;
            w.w = (m & 0xFF000000u) ? w.w : 0.0f;
            __stcs(ov + j, w);
        }
    }
}

extern "C" void kernel_launch(void* const* d_in, const int* in_sizes, int n_in,
                              void* d_out, int out_size) {
    const float* x = nullptr;
    const float* psm = nullptr;
    const int* mask = nullptr;
    for (int i = 0; i < n_in; ++i) {
        if (in_sizes[i] == BB * LL * CC * HW)      x    = (const float*)d_in[i];
        else if (in_sizes[i] == BB * LL * 2 * HW)  psm  = (const float*)d_in[i];
        else if (in_sizes[i] == BB * LL)           mask = (const int*)d_in[i];
    }
    float* out = (float*)d_out;

    // Lazy host-side resources (no device memory involved). Created on the
    // first (uncaptured) correctness call; reused during capture.
    static cudaStream_t s_side = nullptr;
    static cudaEvent_t s_fork = nullptr, s_join = nullptr;
    static bool s_attr_set = false;
    const int sel_smem = (HW + 2048 + 2048) * (int)sizeof(unsigned);  // ~117KB
    if (!s_side) {
        cudaStreamCreateWithFlags(&s_side, cudaStreamNonBlocking);
        cudaEventCreateWithFlags(&s_fork, cudaEventDisableTiming);
        cudaEventCreateWithFlags(&s_join, cudaEventDisableTiming);
    }
    if (!s_attr_set) {
        cudaFuncSetAttribute(select_kernel,
                             cudaFuncAttributeMaxDynamicSharedMemorySize, sel_smem);
        s_attr_set = true;
    }

    const int gx = (HW4 + APPLY_T * UN - 1) / (APPLY_T * UN);  // 7
    const dim3 agrid(gx, CC, NSLICE);

    // Fork: select on side stream, easy-apply concurrently on main stream.
    cudaEventRecord(s_fork, 0);
    cudaStreamWaitEvent(s_side, s_fork, 0);
    select_kernel<<<NSLICE, 1024, sel_smem, s_side>>>(psm);
    cudaEventRecord(s_join, s_side);

    apply_easy_kernel<<<agrid, APPLY_T>>>(x, mask, out);

    // Join: masked apply needs g_fmask from select.
    cudaStreamWaitEvent(0, s_join, 0);
    apply_masked_kernel<<<agrid, APPLY_T>>>(x, mask, out);
}

// round 5
// speedup vs baseline: 2.6442x; 1.0831x over previous
#include <cuda_runtime.h>

#define BB 4
#define LL 5
#define CC 256
#define HW 25200
#define KSEL 1024
#define NSLICE (BB*LL)
#define HW4 (HW/4)
#define UN 4          // float4s per thread in apply
#define APPLY_T 256

// scratch (no allocations allowed)
__device__ unsigned g_fmask[NSLICE * HW4];    // 4 bytes per uint, 1 byte per hw

__device__ __forceinline__ unsigned f2ord(float f) {
    unsigned u = __float_as_uint(f);
    return u ^ ((unsigned)((int)u >> 31) | 0x80000000u);  // monotone float->uint
}

// Fused: compute keys (smem-resident), 3-pass radix select of K-th largest,
// write byte mask. One block per (b,l) slice.
__global__ void select_kernel(const float* __restrict__ psm) {
    extern __shared__ unsigned sm[];
    unsigned* keys = sm;              // HW
    unsigned* hist = sm + HW;         // 2048
    unsigned* aux  = hist + 2048;     // 2048
    __shared__ unsigned s_prefix;
    __shared__ int s_k, s_sel;

    const int slice = blockIdx.x;
    const int b = slice / LL;
    const int tid = threadIdx.x;
    const int nt = blockDim.x;

    const float* __restrict__ pl = psm + (size_t)slice * 2 * HW;     // (b,l,0,:)
    const float* __restrict__ p0 = psm + (size_t)(b * LL) * 2 * HW;  // (b,0,0,:)
    for (int j = tid; j < HW; j += nt) {
        float d0 = pl[j]      - p0[j];
        float d1 = pl[j + HW] - p0[j + HW];
        keys[j] = f2ord(fmaxf(d0, d1));
    }
    if (tid == 0) { s_prefix = 0u; s_k = KSEL; }
    unsigned decided = 0u;
    __syncthreads();

    const int shifts[3] = {21, 10, 0};
    const int nbitsA[3] = {11, 11, 10};

    #pragma unroll
    for (int p = 0; p < 3; ++p) {
        const int shift = shifts[p];
        const int nb = 1 << nbitsA[p];
        const unsigned bm = (unsigned)nb - 1u;

        for (int j = tid; j < nb; j += nt) hist[j] = 0u;
        __syncthreads();

        const unsigned prefix = s_prefix;
        const int k = s_k;   // stable since previous pass's final barrier
        for (int j = tid; j < HW; j += nt) {
            unsigned u = keys[j];
            if ((u & decided) == prefix)
                atomicAdd(&hist[(u >> shift) & bm], 1u);
        }
        __syncthreads();

        // parallel suffix-sum over nb bins (ping-pong hist<->aux)
        unsigned* src = hist;
        unsigned* dst = aux;
        for (int d = 1; d < nb; d <<= 1) {
            for (int j = tid; j < nb; j += nt)
                dst[j] = src[j] + ((j + d < nb) ? src[j + d] : 0u);
            __syncthreads();
            unsigned* t = src; src = dst; dst = t;
        }
        // src[j] = count of keys with digit >= j (within prefix class)
        for (int j = tid; j < nb; j += nt) {
            int sj  = (int)src[j];
            int sj1 = (j + 1 < nb) ? (int)src[j + 1] : 0;
            if (sj >= k && sj1 < k) {       // unique j
                s_sel = j;
                s_k   = k - sj1;
            }
        }
        __syncthreads();
        if (tid == 0) s_prefix = prefix | ((unsigned)s_sel << shift);
        decided |= bm << shift;
        __syncthreads();
    }

    const unsigned thresh = s_prefix;   // exact K-th largest key
    unsigned* fm = g_fmask + slice * HW4;
    const uint4* k4 = (const uint4*)keys;
    for (int j4 = tid; j4 < HW4; j4 += nt) {
        uint4 kk = k4[j4];
        unsigned b0 = (kk.x >= thresh) ? 1u : 0u;
        unsigned b1 = (kk.y >= thresh) ? 1u : 0u;
        unsigned b2 = (kk.z >= thresh) ? 1u : 0u;
        unsigned b3 = (kk.w >= thresh) ? 1u : 0u;
        fm[j4] = b0 | (b1 << 8) | (b2 << 16) | (b3 << 24);
    }
}

// Easy slices: l==0 -> copy x, (l>0 && mask==0) -> zeros. No fmask dependency.
// grid (ceil(HW4/(T*UN)), C, NSLICE)
__global__ void apply_easy_kernel(const float* __restrict__ x,
                                  const int* __restrict__ mask,
                                  float* __restrict__ out) {
    const int slice = blockIdx.z;
    const int l = slice % LL;
    const bool is_ego = (l == 0);
    if (!is_ego && mask[slice] != 0) return;   // masked path handled elsewhere

    const int c = blockIdx.y;
    const size_t base = ((size_t)slice * CC + c) * (size_t)HW4;
    const float4* __restrict__ xv = (const float4*)x + base;
    float4* __restrict__ ov = (float4*)out + base;
    const int j0 = blockIdx.x * (APPLY_T * UN) + threadIdx.x;

    if (is_ego) {
        #pragma unroll
        for (int u = 0; u < UN; ++u) {
            int j = j0 + u * APPLY_T;
            if (j < HW4) __stcs(ov + j, __ldcs(xv + j));
        }
    } else {
        const float4 z = make_float4(0.f, 0.f, 0.f, 0.f);
        #pragma unroll
        for (int u = 0; u < UN; ++u) {
            int j = j0 + u * APPLY_T;
            if (j < HW4) __stcs(ov + j, z);
        }
    }
}

// Masked slices: l>0 && mask!=0 -> x * fmask. Sparse reads: only ~4% of
// elements survive, so load the fmask word first (L1/L2-resident) and issue
// the 16B x load only when any of its 4 lanes is kept. Predicated-off lanes
// fetch no sectors -> masked-slice DRAM reads drop ~70%.
__global__ void apply_masked_kernel(const float* __restrict__ x,
                                    const int* __restrict__ mask,
                                    float* __restrict__ out) {
    const int slice = blockIdx.z;
    const int l = slice % LL;
    if (l == 0 || mask[slice] == 0) return;    // handled by easy kernel

    const int c = blockIdx.y;
    const size_t base = ((size_t)slice * CC + c) * (size_t)HW4;
    const float4* __restrict__ xv = (const float4*)x + base;
    float4* __restrict__ ov = (float4*)out + base;
    const int j0 = blockIdx.x * (APPLY_T * UN) + threadIdx.x;

    const unsigned* __restrict__ fm = g_fmask + slice * HW4;
    unsigned m4[UN];
    #pragma unroll
    for (int u = 0; u < UN; ++u) {
        int j = j0 + u * APPLY_T;
        m4[u] = (j < HW4) ? __ldg(fm + j) : 0u;
    }
    float4 v[UN];
    #pragma unroll
    for (int u = 0; u < UN; ++u) {
        int j = j0 + u * APPLY_T;
        if (j < HW4 && m4[u] != 0u) v[u] = __ldcs(xv + j);
    }
    #pragma unroll
    for (int u = 0; u < UN; ++u) {
        int j = j0 + u * APPLY_T;
        if (j >= HW4) continue;
        float4 w = make_float4(0.f, 0.f, 0.f, 0.f);
        unsigned m = m4[u];
        if (m != 0u) {
            if (m & 0x000000FFu) w.x = v[u].x;
            if (m & 0x0000FF00u) w.y = v[u].y;
            if (m & 0x00FF0000u) w.z = v[u].z;
            if (m & 0xFF000000u) w.w = v[u].w;
        }
        __stcs(ov + j, w);
    }
}

extern "C" void kernel_launch(void* const* d_in, const int* in_sizes, int n_in,
                              void* d_out, int out_size) {
    const float* x = nullptr;
    const float* psm = nullptr;
    const int* mask = nullptr;
    for (int i = 0; i < n_in; ++i) {
        if (in_sizes[i] == BB * LL * CC * HW)      x    = (const float*)d_in[i];
        else if (in_sizes[i] == BB * LL * 2 * HW)  psm  = (const float*)d_in[i];
        else if (in_sizes[i] == BB * LL)           mask = (const int*)d_in[i];
    }
    float* out = (float*)d_out;

    // Lazy host-side resources (no device memory involved).
    static cudaStream_t s_side = nullptr;
    static cudaEvent_t s_fork = nullptr, s_join = nullptr;
    static bool s_attr_set = false;
    const int sel_smem = (HW + 2048 + 2048) * (int)sizeof(unsigned);  // ~117KB
    if (!s_side) {
        cudaStreamCreateWithFlags(&s_side, cudaStreamNonBlocking);
        cudaEventCreateWithFlags(&s_fork, cudaEventDisableTiming);
        cudaEventCreateWithFlags(&s_join, cudaEventDisableTiming);
    }
    if (!s_attr_set) {
        cudaFuncSetAttribute(select_kernel,
                             cudaFuncAttributeMaxDynamicSharedMemorySize, sel_smem);
        s_attr_set = true;
    }

    const int gx = (HW4 + APPLY_T * UN - 1) / (APPLY_T * UN);  // 7
    const dim3 agrid(gx, CC, NSLICE);

    // Side stream: select -> masked-apply (critical path ~22+40us).
    // Main stream: easy-apply (~60us) runs concurrently with both.
    cudaEventRecord(s_fork, 0);
    cudaStreamWaitEvent(s_side, s_fork, 0);
    select_kernel<<<NSLICE, 1024, sel_smem, s_side>>>(psm);
    apply_masked_kernel<<<agrid, APPLY_T, 0, s_side>>>(x, mask, out);
    cudaEventRecord(s_join, s_side);

    apply_easy_kernel<<<agrid, APPLY_T>>>(x, mask, out);

    cudaStreamWaitEvent(0, s_join, 0);
}